// round 1
// baseline (speedup 1.0000x reference)
#include <cuda_runtime.h>
#include <math.h>

#define BATCH 16
#define NPTS  2048
#define DIM   512
#define BQ 64
#define BK 64
#define KC 16

// Per-batch accumulators: M1 = sum_n src[n] * matched[n]^T (9), mm = sum_n matched[n] (3)
__device__ float g_M1[BATCH * 9];
__device__ float g_mm[BATCH * 3];

__global__ void zero_kernel() {
    int i = threadIdx.x;
    if (i < BATCH * 9) g_M1[i] = 0.f;
    if (i < BATCH * 3) g_mm[i] = 0.f;
}

// Streaming soft-correspondence attention:
// queries = src_embed (axis n), keys = tgt_embed (axis m), values = tgt (3 floats).
// Single-pass softmax (no max subtraction: logits bounded ~|40|, exp safe in fp32).
__global__ __launch_bounds__(256) void attn_kernel(
    const float* __restrict__ src, const float* __restrict__ tgt,
    const float* __restrict__ src_embed, const float* __restrict__ tgt_embed)
{
    const int tilesPerBatch = NPTS / BQ;
    const int b  = blockIdx.x / tilesPerBatch;
    const int q0 = (blockIdx.x % tilesPerBatch) * BQ;
    const int tid = threadIdx.x;
    const int tx = tid & 15, ty = tid >> 4;

    __shared__ float Qs[KC][BQ];     // k-major: Qs[k][n]
    __shared__ float Ks[KC][BK];     // k-major: Ks[k][m]
    __shared__ float Vs[BK * 3];     // tgt values for current key tile
    __shared__ float blk[12];        // per-block partial M1(9) + mm(3)

    if (tid < 12) blk[tid] = 0.f;

    const float* qb = src_embed + (size_t)b * NPTS * DIM;
    const float* kb = tgt_embed + (size_t)b * NPTS * DIM;
    const float* vb = tgt       + (size_t)b * NPTS * 3;

    const int n_l = tid & 63;          // row within tile (64 rows)
    const int k_l = (tid >> 6) << 2;   // 4-wide column group within KC=16

    float denom[4] = {0.f, 0.f, 0.f, 0.f};
    float num[4][3] = {};

    for (int m0 = 0; m0 < NPTS; m0 += BK) {
        float acc[4][4] = {};
        for (int kc = 0; kc < DIM; kc += KC) {
            __syncthreads();
            // transpose-load Q/K chunks into k-major smem (conflict-free stores)
            float4 q4 = *(const float4*)(qb + (size_t)(q0 + n_l) * DIM + kc + k_l);
            Qs[k_l + 0][n_l] = q4.x; Qs[k_l + 1][n_l] = q4.y;
            Qs[k_l + 2][n_l] = q4.z; Qs[k_l + 3][n_l] = q4.w;
            float4 k4 = *(const float4*)(kb + (size_t)(m0 + n_l) * DIM + kc + k_l);
            Ks[k_l + 0][n_l] = k4.x; Ks[k_l + 1][n_l] = k4.y;
            Ks[k_l + 2][n_l] = k4.z; Ks[k_l + 3][n_l] = k4.w;
            if (kc == 0 && tid < BK * 3) Vs[tid] = vb[m0 * 3 + tid];
            __syncthreads();
            #pragma unroll
            for (int k = 0; k < KC; k++) {
                float4 q  = *(const float4*)&Qs[k][ty << 2];
                float4 kk = *(const float4*)&Ks[k][tx << 2];
                acc[0][0] += q.x * kk.x; acc[0][1] += q.x * kk.y;
                acc[0][2] += q.x * kk.z; acc[0][3] += q.x * kk.w;
                acc[1][0] += q.y * kk.x; acc[1][1] += q.y * kk.y;
                acc[1][2] += q.y * kk.z; acc[1][3] += q.y * kk.w;
                acc[2][0] += q.z * kk.x; acc[2][1] += q.z * kk.y;
                acc[2][2] += q.z * kk.z; acc[2][3] += q.z * kk.w;
                acc[3][0] += q.w * kk.x; acc[3][1] += q.w * kk.y;
                acc[3][2] += q.w * kk.z; acc[3][3] += q.w * kk.w;
            }
        }
        // epilogue: exp + streaming weighted sums (reads Vs; next tile's first
        // __syncthreads protects Vs from being overwritten while in use)
        #pragma unroll
        for (int i = 0; i < 4; i++) {
            #pragma unroll
            for (int j = 0; j < 4; j++) {
                float e = expf(acc[i][j] * (1.f / 3.f));
                int m = (tx << 2) + j;
                denom[i]  += e;
                num[i][0] += e * Vs[m * 3 + 0];
                num[i][1] += e * Vs[m * 3 + 1];
                num[i][2] += e * Vs[m * 3 + 2];
            }
        }
    }

    // reduce over tx (key dimension) via butterfly shuffles within 16-lane groups
    #pragma unroll
    for (int off = 8; off; off >>= 1) {
        #pragma unroll
        for (int i = 0; i < 4; i++) {
            denom[i]  += __shfl_xor_sync(0xFFFFFFFFu, denom[i],  off);
            num[i][0] += __shfl_xor_sync(0xFFFFFFFFu, num[i][0], off);
            num[i][1] += __shfl_xor_sync(0xFFFFFFFFu, num[i][1], off);
            num[i][2] += __shfl_xor_sync(0xFFFFFFFFu, num[i][2], off);
        }
    }

    if (tx == 0) {
        float p[9] = {0,0,0,0,0,0,0,0,0};
        float pm[3] = {0,0,0};
        #pragma unroll
        for (int i = 0; i < 4; i++) {
            int n = q0 + (ty << 2) + i;
            float inv = 1.f / denom[i];
            float m0c = num[i][0] * inv, m1c = num[i][1] * inv, m2c = num[i][2] * inv;
            const float* sp = src + (size_t)b * NPTS * 3 + (size_t)n * 3;
            float s0 = sp[0], s1 = sp[1], s2 = sp[2];
            p[0] += s0 * m0c; p[1] += s0 * m1c; p[2] += s0 * m2c;
            p[3] += s1 * m0c; p[4] += s1 * m1c; p[5] += s1 * m2c;
            p[6] += s2 * m0c; p[7] += s2 * m1c; p[8] += s2 * m2c;
            pm[0] += m0c; pm[1] += m1c; pm[2] += m2c;
        }
        #pragma unroll
        for (int k = 0; k < 9; k++) atomicAdd(&blk[k], p[k]);
        #pragma unroll
        for (int c = 0; c < 3; c++) atomicAdd(&blk[9 + c], pm[c]);
    }
    __syncthreads();
    if (tid < 9)                 atomicAdd(&g_M1[b * 9 + tid], blk[tid]);
    if (tid >= 9 && tid < 12)    atomicAdd(&g_mm[b * 3 + (tid - 9)], blk[tid]);
}

// Per-batch: assemble H, compute R = polar(H^T) via scaled Newton (== V U^T of
// SVD H = U S V^T, invariant to SVD ambiguities), reflection fix, and t.
__global__ void finalize_kernel(const float* __restrict__ src, float* __restrict__ out) {
    const int b = blockIdx.x;
    const int tid = threadIdx.x;
    __shared__ float red[256 * 3];

    float s0 = 0.f, s1 = 0.f, s2 = 0.f;
    const float* sb = src + (size_t)b * NPTS * 3;
    for (int n = tid; n < NPTS; n += 256) {
        s0 += sb[n * 3 + 0]; s1 += sb[n * 3 + 1]; s2 += sb[n * 3 + 2];
    }
    red[tid * 3 + 0] = s0; red[tid * 3 + 1] = s1; red[tid * 3 + 2] = s2;
    __syncthreads();
    for (int s = 128; s; s >>= 1) {
        if (tid < s) {
            red[tid * 3 + 0] += red[(tid + s) * 3 + 0];
            red[tid * 3 + 1] += red[(tid + s) * 3 + 1];
            red[tid * 3 + 2] += red[(tid + s) * 3 + 2];
        }
        __syncthreads();
    }

    if (tid == 0) {
        const double Nd = (double)NPTS;
        double sm[3] = { red[0] / Nd, red[1] / Nd, red[2] / Nd };
        double mm[3] = { (double)g_mm[b*3+0] / Nd, (double)g_mm[b*3+1] / Nd,
                         (double)g_mm[b*3+2] / Nd };
        double H[3][3];
        for (int i = 0; i < 3; i++)
            for (int j = 0; j < 3; j++)
                H[i][j] = (double)g_M1[b * 9 + i * 3 + j] - Nd * sm[i] * mm[j];

        // A = H^T, normalized; Newton polar iteration with determinantal scaling
        double A[3][3];
        double f = 0.0;
        for (int i = 0; i < 3; i++)
            for (int j = 0; j < 3; j++) { A[i][j] = H[j][i]; f += A[i][j] * A[i][j]; }
        f = 1.0 / sqrt(f);
        for (int i = 0; i < 3; i++)
            for (int j = 0; j < 3; j++) A[i][j] *= f;

        for (int it = 0; it < 30; it++) {
            double C[3][3];
            C[0][0] =  A[1][1]*A[2][2] - A[1][2]*A[2][1];
            C[0][1] = -(A[1][0]*A[2][2] - A[1][2]*A[2][0]);
            C[0][2] =  A[1][0]*A[2][1] - A[1][1]*A[2][0];
            C[1][0] = -(A[0][1]*A[2][2] - A[0][2]*A[2][1]);
            C[1][1] =  A[0][0]*A[2][2] - A[0][2]*A[2][0];
            C[1][2] = -(A[0][0]*A[2][1] - A[0][1]*A[2][0]);
            C[2][0] =  A[0][1]*A[1][2] - A[0][2]*A[1][1];
            C[2][1] = -(A[0][0]*A[1][2] - A[0][2]*A[1][0]);
            C[2][2] =  A[0][0]*A[1][1] - A[0][1]*A[1][0];
            double det = A[0][0]*C[0][0] + A[0][1]*C[0][1] + A[0][2]*C[0][2];
            double mu = pow(fabs(det), -1.0 / 3.0);
            double idm = 1.0 / (det * mu);
            for (int i = 0; i < 3; i++)
                for (int j = 0; j < 3; j++)
                    A[i][j] = 0.5 * (mu * A[i][j] + C[i][j] * idm);
        }

        double detR =
            A[0][0]*(A[1][1]*A[2][2] - A[1][2]*A[2][1])
          - A[0][1]*(A[1][0]*A[2][2] - A[1][2]*A[2][0])
          + A[0][2]*(A[1][0]*A[2][1] - A[1][1]*A[2][0]);

        double R[3][3];
        for (int i = 0; i < 3; i++)
            for (int j = 0; j < 3; j++) R[i][j] = A[i][j];
        if (detR < 0.0) { R[2][0] = -R[2][0]; R[2][1] = -R[2][1]; R[2][2] = -R[2][2]; }

        double t[3];
        for (int j = 0; j < 3; j++)
            t[j] = mm[j] - (sm[0] * R[j][0] + sm[1] * R[j][1] + sm[2] * R[j][2]);

        for (int i = 0; i < 3; i++)
            for (int j = 0; j < 3; j++)
                out[b * 9 + i * 3 + j] = (float)R[i][j];
        for (int j = 0; j < 3; j++)
            out[BATCH * 9 + b * 3 + j] = (float)t[j];
    }
}

extern "C" void kernel_launch(void* const* d_in, const int* in_sizes, int n_in,
                              void* d_out, int out_size) {
    const float* src = (const float*)d_in[0];
    const float* tgt = (const float*)d_in[1];
    const float* src_embed = (const float*)d_in[2];
    const float* tgt_embed = (const float*)d_in[3];
    float* out = (float*)d_out;

    zero_kernel<<<1, 192>>>();
    attn_kernel<<<BATCH * (NPTS / BQ), 256>>>(src, tgt, src_embed, tgt_embed);
    finalize_kernel<<<BATCH, 256>>>(src, out);
}

// round 5
// speedup vs baseline: 4.6099x; 4.6099x over previous
#include <cuda_runtime.h>
#include <cuda_bf16.h>
#include <math.h>
#include <stdint.h>

#define BATCH 16
#define NPTS  2048
#define DIM   512

// bf16 hi/lo scratch, plain row-major [B][N][D]
__device__ __align__(16) __nv_bfloat16 g_Qh[BATCH * NPTS * DIM];
__device__ __align__(16) __nv_bfloat16 g_Ql[BATCH * NPTS * DIM];
__device__ __align__(16) __nv_bfloat16 g_Kh[BATCH * NPTS * DIM];
__device__ __align__(16) __nv_bfloat16 g_Kl[BATCH * NPTS * DIM];
__device__ float g_M1[BATCH * 9];
__device__ float g_mm[BATCH * 3];

__device__ __forceinline__ uint32_t smem_u32(const void* p) {
    uint32_t a;
    asm("{ .reg .u64 t; cvta.to.shared.u64 t, %1; cvt.u32.u64 %0, t; }" : "=r"(a) : "l"(p));
    return a;
}
#define CPA(dst, src) \
    asm volatile("cp.async.cg.shared.global [%0], [%1], 16;" :: "r"(dst), "l"(src) : "memory")
#define CPC() asm volatile("cp.async.commit_group;" ::: "memory")
#define CPW(n) asm volatile("cp.async.wait_group %0;" :: "n"(n) : "memory")

__device__ __forceinline__ void ldm4(uint32_t* r, uint32_t a) {
    asm volatile("ldmatrix.sync.aligned.m8n8.x4.shared.b16 {%0,%1,%2,%3}, [%4];"
                 : "=r"(r[0]), "=r"(r[1]), "=r"(r[2]), "=r"(r[3]) : "r"(a));
}
__device__ __forceinline__ void mma16816(float* c, const uint32_t* a, uint32_t b0, uint32_t b1) {
    asm volatile("mma.sync.aligned.m16n8k16.row.col.f32.bf16.bf16.f32 "
                 "{%0,%1,%2,%3},{%4,%5,%6,%7},{%8,%9},{%0,%1,%2,%3};"
                 : "+f"(c[0]), "+f"(c[1]), "+f"(c[2]), "+f"(c[3])
                 : "r"(a[0]), "r"(a[1]), "r"(a[2]), "r"(a[3]), "r"(b0), "r"(b1));
}

__global__ void zero_kernel() {
    int i = threadIdx.x;
    if (i < BATCH * 9) g_M1[i] = 0.f;
    if (i < BATCH * 3) g_mm[i] = 0.f;
}

__global__ void prep_kernel(const float* __restrict__ se, const float* __restrict__ te) {
    const unsigned PER = 16u * 2048u * 128u;  // float4 groups per tensor
    unsigned idx = blockIdx.x * blockDim.x + threadIdx.x;
    if (idx >= 2u * PER) return;
    bool isK = idx >= PER;
    unsigned i = isK ? idx - PER : idx;
    size_t e = (size_t)i * 4;  // element offset in [B*N*D]
    float4 v = *(const float4*)((isK ? te : se) + e);
    if (!isK) { const float s = 1.f / 3.f; v.x *= s; v.y *= s; v.z *= s; v.w *= s; }
    __nv_bfloat16 h0 = __float2bfloat16_rn(v.x), h1 = __float2bfloat16_rn(v.y);
    __nv_bfloat16 h2 = __float2bfloat16_rn(v.z), h3 = __float2bfloat16_rn(v.w);
    __nv_bfloat16 l0 = __float2bfloat16_rn(v.x - __bfloat162float(h0));
    __nv_bfloat16 l1 = __float2bfloat16_rn(v.y - __bfloat162float(h1));
    __nv_bfloat16 l2 = __float2bfloat16_rn(v.z - __bfloat162float(h2));
    __nv_bfloat16 l3 = __float2bfloat16_rn(v.w - __bfloat162float(h3));
    uint2 hp, lp;
    hp.x = (uint32_t)__bfloat16_as_ushort(h0) | ((uint32_t)__bfloat16_as_ushort(h1) << 16);
    hp.y = (uint32_t)__bfloat16_as_ushort(h2) | ((uint32_t)__bfloat16_as_ushort(h3) << 16);
    lp.x = (uint32_t)__bfloat16_as_ushort(l0) | ((uint32_t)__bfloat16_as_ushort(l1) << 16);
    lp.y = (uint32_t)__bfloat16_as_ushort(l2) | ((uint32_t)__bfloat16_as_ushort(l3) << 16);
    if (isK) { *(uint2*)(g_Kh + e) = hp; *(uint2*)(g_Kl + e) = lp; }
    else     { *(uint2*)(g_Qh + e) = hp; *(uint2*)(g_Ql + e) = lp; }
}

// Flash-style streaming attention on HMMA. CTA: 128 queries x full keys.
// Stage = 4 buffers (Qh,Ql,Kh,Kl) of [128 rows][64 bf16] SW128 = 16KB each.
#define STAGE_SZ 65536
__global__ void __launch_bounds__(256, 1)
attn_mma_kernel(const float* __restrict__ src, const float* __restrict__ tgt) {
    extern __shared__ unsigned char dyn_smem[];
    __shared__ float4 v_smem[128];
    __shared__ float  red[128][4];
    const uint32_t sb = smem_u32(dyn_smem);
    const int tid = threadIdx.x, lane = tid & 31, wid = tid >> 5;
    const int wm = wid >> 1, wn = wid & 1;  // 4x2 warp grid: 32m x 64n
    const int b = blockIdx.x >> 4, qt = blockIdx.x & 15;

    if (tid < 128) { red[tid][0] = 0.f; red[tid][1] = 0.f; red[tid][2] = 0.f; red[tid][3] = 0.f; }

    float acc[2][8][4];
    #pragma unroll
    for (int s = 0; s < 2; s++)
        #pragma unroll
        for (int ns = 0; ns < 8; ns++)
            #pragma unroll
            for (int c = 0; c < 4; c++) acc[s][ns][c] = 0.f;
    float den[4] = {0, 0, 0, 0}, num[4][3] = {};

    // cp.async issue helper data
    const int lrow = (tid * 2) >> 4;        // unused placeholder avoided; compute per r
    (void)lrow;

    // ldmatrix lane addressing (constant per thread)
    const int la_row = ((lane >> 3) & 1) * 8 + (lane & 7);
    const int la_k   = (lane >> 4) & 1;
    const int lb_row = ((lane >> 4) & 1) * 8 + (lane & 7);
    const int lb_k   = (lane >> 3) & 1;

    // issue chunk cidx into stage st
    auto issue = [&](int cidx, int st) {
        const int kt = cidx >> 3, kc = cidx & 7;
        const uint32_t base = sb + st * STAGE_SZ;
        #pragma unroll
        for (int r = 0; r < 4; r++) {
            int lin = tid + r * 256;
            int row = lin >> 3, kg = lin & 7;
            uint32_t off = (uint32_t)row * 128u + (uint32_t)((kg ^ (row & 7)) << 4);
            size_t qe = ((size_t)(b * NPTS + qt * 128 + row)) * DIM + kc * 64 + kg * 8;
            size_t ke = ((size_t)(b * NPTS + kt * 128 + row)) * DIM + kc * 64 + kg * 8;
            CPA(base + off,             g_Qh + qe);
            CPA(base + 16384 + off,     g_Ql + qe);
            CPA(base + 32768 + off,     g_Kh + ke);
            CPA(base + 49152 + off,     g_Kl + ke);
        }
    };

    __syncthreads();
    issue(0, 0); CPC();

    for (int cidx = 0; cidx < 128; cidx++) {
        const int st = cidx & 1;
        if (cidx + 1 < 128) { issue(cidx + 1, st ^ 1); CPC(); CPW(1); }
        else { CPW(0); }
        __syncthreads();

        const uint32_t qh = sb + st * STAGE_SZ, ql = qh + 16384;
        const uint32_t kh = qh + 32768, kl = qh + 49152;
        #pragma unroll
        for (int j = 0; j < 4; j++) {
            uint32_t ah[8], al[8];
            #pragma unroll
            for (int s = 0; s < 2; s++) {
                int row = wm * 32 + s * 16 + la_row;
                uint32_t off = (uint32_t)row * 128u +
                               (uint32_t)(((j * 2 + la_k) ^ (row & 7)) << 4);
                ldm4(ah + s * 4, qh + off);
                ldm4(al + s * 4, ql + off);
            }
            #pragma unroll
            for (int g = 0; g < 4; g++) {
                int row = wn * 64 + g * 16 + lb_row;
                uint32_t off = (uint32_t)row * 128u +
                               (uint32_t)(((j * 2 + lb_k) ^ (row & 7)) << 4);
                uint32_t bh[4], bl[4];
                ldm4(bh, kh + off);
                ldm4(bl, kl + off);
                #pragma unroll
                for (int h = 0; h < 2; h++) {
                    #pragma unroll
                    for (int s = 0; s < 2; s++) {
                        float* a = acc[s][g * 2 + h];
                        mma16816(a, ah + s * 4, bh[h * 2], bh[h * 2 + 1]);
                        mma16816(a, al + s * 4, bh[h * 2], bh[h * 2 + 1]);
                        mma16816(a, ah + s * 4, bl[h * 2], bl[h * 2 + 1]);
                    }
                }
            }
        }

        if ((cidx & 7) == 7) {  // key tile complete: softmax-stream epilogue
            const int kt = cidx >> 3;
            __syncthreads();
            if (tid < 128) {
                const float* vp = tgt + ((size_t)(b * NPTS + kt * 128 + tid)) * 3;
                v_smem[tid] = make_float4(vp[0], vp[1], vp[2], 0.f);
            }
            __syncthreads();
            #pragma unroll
            for (int ns = 0; ns < 8; ns++) {
                float4 v0 = v_smem[wn * 64 + ns * 8 + 2 * (lane & 3)];
                float4 v1 = v_smem[wn * 64 + ns * 8 + 2 * (lane & 3) + 1];
                #pragma unroll
                for (int s = 0; s < 2; s++) {
                    #pragma unroll
                    for (int cp = 0; cp < 2; cp++) {
                        float e0 = __expf(acc[s][ns][cp * 2]);
                        float e1 = __expf(acc[s][ns][cp * 2 + 1]);
                        int qi = s * 2 + cp;
                        den[qi] += e0 + e1;
                        num[qi][0] += e0 * v0.x + e1 * v1.x;
                        num[qi][1] += e0 * v0.y + e1 * v1.y;
                        num[qi][2] += e0 * v0.z + e1 * v1.z;
                        acc[s][ns][cp * 2] = 0.f;
                        acc[s][ns][cp * 2 + 1] = 0.f;
                    }
                }
            }
        }
        __syncthreads();
    }

    // reduce den/num over the 4 lanes sharing each query row
    #pragma unroll
    for (int o = 1; o <= 2; o <<= 1) {
        #pragma unroll
        for (int qi = 0; qi < 4; qi++) {
            den[qi] += __shfl_xor_sync(0xFFFFFFFFu, den[qi], o);
            num[qi][0] += __shfl_xor_sync(0xFFFFFFFFu, num[qi][0], o);
            num[qi][1] += __shfl_xor_sync(0xFFFFFFFFu, num[qi][1], o);
            num[qi][2] += __shfl_xor_sync(0xFFFFFFFFu, num[qi][2], o);
        }
    }
    if ((lane & 3) == 0) {
        #pragma unroll
        for (int qi = 0; qi < 4; qi++) {
            int q = wm * 32 + (qi >> 1) * 16 + (qi & 1) * 8 + (lane >> 2);
            atomicAdd(&red[q][0], den[qi]);
            atomicAdd(&red[q][1], num[qi][0]);
            atomicAdd(&red[q][2], num[qi][1]);
            atomicAdd(&red[q][3], num[qi][2]);
        }
    }
    __syncthreads();

    if (tid < 128) {
        const int n = qt * 128 + tid;
        const float inv = 1.f / red[tid][0];
        const float m0 = red[tid][1] * inv, m1 = red[tid][2] * inv, m2 = red[tid][3] * inv;
        const float* sp = src + ((size_t)(b * NPTS + n)) * 3;
        const float s0 = __ldg(sp), s1 = __ldg(sp + 1), s2 = __ldg(sp + 2);
        float vals[12] = { s0 * m0, s0 * m1, s0 * m2, s1 * m0, s1 * m1, s1 * m2,
                           s2 * m0, s2 * m1, s2 * m2, m0, m1, m2 };
        #pragma unroll
        for (int o = 16; o; o >>= 1)
            #pragma unroll
            for (int i = 0; i < 12; i++)
                vals[i] += __shfl_xor_sync(0xFFFFFFFFu, vals[i], o);
        if (lane == 0) {
            #pragma unroll
            for (int i = 0; i < 9; i++) atomicAdd(&g_M1[b * 9 + i], vals[i]);
            #pragma unroll
            for (int c = 0; c < 3; c++) atomicAdd(&g_mm[b * 3 + c], vals[9 + c]);
        }
    }
}

__global__ void finalize_kernel(const float* __restrict__ src, float* __restrict__ out) {
    const int b = blockIdx.x, tid = threadIdx.x;
    __shared__ float red[256 * 3];
    float s0 = 0.f, s1 = 0.f, s2 = 0.f;
    const float* sb = src + (size_t)b * NPTS * 3;
    for (int n = tid; n < NPTS; n += 256) {
        s0 += sb[n * 3]; s1 += sb[n * 3 + 1]; s2 += sb[n * 3 + 2];
    }
    red[tid * 3] = s0; red[tid * 3 + 1] = s1; red[tid * 3 + 2] = s2;
    __syncthreads();
    for (int s = 128; s; s >>= 1) {
        if (tid < s)
            for (int c = 0; c < 3; c++) red[tid * 3 + c] += red[(tid + s) * 3 + c];
        __syncthreads();
    }
    if (tid == 0) {
        const double Nd = (double)NPTS;
        double sm[3] = { red[0] / Nd, red[1] / Nd, red[2] / Nd };
        double mm[3] = { g_mm[b*3] / Nd, g_mm[b*3+1] / Nd, g_mm[b*3+2] / Nd };
        double A[3][3]; double f = 0.0;
        for (int i = 0; i < 3; i++)
            for (int j = 0; j < 3; j++) {
                double h = (double)g_M1[b * 9 + j * 3 + i] - Nd * sm[j] * mm[i];
                A[i][j] = h; f += h * h;   // A = H^T
            }
        f = 1.0 / sqrt(f);
        for (int i = 0; i < 3; i++)
            for (int j = 0; j < 3; j++) A[i][j] *= f;
        for (int it = 0; it < 25; it++) {
            double C[3][3];
            C[0][0] =  A[1][1]*A[2][2] - A[1][2]*A[2][1];
            C[0][1] = -(A[1][0]*A[2][2] - A[1][2]*A[2][0]);
            C[0][2] =  A[1][0]*A[2][1] - A[1][1]*A[2][0];
            C[1][0] = -(A[0][1]*A[2][2] - A[0][2]*A[2][1]);
            C[1][1] =  A[0][0]*A[2][2] - A[0][2]*A[2][0];
            C[1][2] = -(A[0][0]*A[2][1] - A[0][1]*A[2][0]);
            C[2][0] =  A[0][1]*A[1][2] - A[0][2]*A[1][1];
            C[2][1] = -(A[0][0]*A[1][2] - A[0][2]*A[1][0]);
            C[2][2] =  A[0][0]*A[1][1] - A[0][1]*A[1][0];
            double det = A[0][0]*C[0][0] + A[0][1]*C[0][1] + A[0][2]*C[0][2];
            double mu = pow(fabs(det), -1.0 / 3.0);
            double idm = 1.0 / (det * mu);
            for (int i = 0; i < 3; i++)
                for (int j = 0; j < 3; j++)
                    A[i][j] = 0.5 * (mu * A[i][j] + C[i][j] * idm);
        }
        double detR = A[0][0]*(A[1][1]*A[2][2]-A[1][2]*A[2][1])
                    - A[0][1]*(A[1][0]*A[2][2]-A[1][2]*A[2][0])
                    + A[0][2]*(A[1][0]*A[2][1]-A[1][1]*A[2][0]);
        if (detR < 0.0) { A[2][0] = -A[2][0]; A[2][1] = -A[2][1]; A[2][2] = -A[2][2]; }
        for (int i = 0; i < 3; i++)
            for (int j = 0; j < 3; j++)
                out[b * 9 + i * 3 + j] = (float)A[i][j];
        for (int j = 0; j < 3; j++)
            out[BATCH * 9 + b * 3 + j] =
                (float)(mm[j] - (sm[0] * A[j][0] + sm[1] * A[j][1] + sm[2] * A[j][2]));
    }
}

extern "C" void kernel_launch(void* const* d_in, const int* in_sizes, int n_in,
                              void* d_out, int out_size) {
    const float* src = (const float*)d_in[0];
    const float* tgt = (const float*)d_in[1];
    const float* src_embed = (const float*)d_in[2];
    const float* tgt_embed = (const float*)d_in[3];
    float* out = (float*)d_out;

    static int init_done = 0;
    if (!init_done) {
        cudaFuncSetAttribute(attn_mma_kernel,
                             cudaFuncAttributeMaxDynamicSharedMemorySize, 2 * STAGE_SZ);
        init_done = 1;
    }
    zero_kernel<<<1, 192>>>();
    prep_kernel<<<32768, 256>>>(src_embed, tgt_embed);
    attn_mma_kernel<<<BATCH * 16, 256, 2 * STAGE_SZ>>>(src, tgt);
    finalize_kernel<<<BATCH, 256>>>(src, out);
}

// round 7
// speedup vs baseline: 4.6308x; 1.0045x over previous
#include <cuda_runtime.h>
#include <cuda_fp16.h>
#include <math.h>
#include <stdint.h>

#define BATCH 16
#define NPTS  2048
#define DIM   512

// fp16 hi/lo scratch, row-major [B][N][D]; Q has 1/3 folded in before split.
__device__ __align__(16) __half g_Qh[BATCH * NPTS * DIM];
__device__ __align__(16) __half g_Ql[BATCH * NPTS * DIM];
__device__ __align__(16) __half g_Kh[BATCH * NPTS * DIM];
__device__ __align__(16) __half g_Kl[BATCH * NPTS * DIM];
__device__ float g_M1[BATCH * 9];
__device__ float g_mm[BATCH * 3];

__device__ __forceinline__ uint32_t smem_u32(const void* p) {
    uint32_t a;
    asm("{ .reg .u64 t; cvta.to.shared.u64 t, %1; cvt.u32.u64 %0, t; }" : "=r"(a) : "l"(p));
    return a;
}
#define CPA(dst, src) \
    asm volatile("cp.async.cg.shared.global [%0], [%1], 16;" :: "r"(dst), "l"(src) : "memory")
#define CPC() asm volatile("cp.async.commit_group;" ::: "memory")
#define CPW(n) asm volatile("cp.async.wait_group %0;" :: "n"(n) : "memory")

__device__ __forceinline__ void ldm4(uint32_t* r, uint32_t a) {
    asm volatile("ldmatrix.sync.aligned.m8n8.x4.shared.b16 {%0,%1,%2,%3}, [%4];"
                 : "=r"(r[0]), "=r"(r[1]), "=r"(r[2]), "=r"(r[3]) : "r"(a));
}
__device__ __forceinline__ void mma16816(float* c, const uint32_t* a, uint32_t b0, uint32_t b1) {
    asm volatile("mma.sync.aligned.m16n8k16.row.col.f32.f16.f16.f32 "
                 "{%0,%1,%2,%3},{%4,%5,%6,%7},{%8,%9},{%0,%1,%2,%3};"
                 : "+f"(c[0]), "+f"(c[1]), "+f"(c[2]), "+f"(c[3])
                 : "r"(a[0]), "r"(a[1]), "r"(a[2]), "r"(a[3]), "r"(b0), "r"(b1));
}

// fp32 -> fp16 hi + fp16 lo (Q scaled by 1/3 first); block 0 zeroes accumulators.
__global__ void prep_kernel(const float* __restrict__ se, const float* __restrict__ te) {
    if (blockIdx.x == 0 && threadIdx.x < 192) {
        int i = threadIdx.x;
        if (i < BATCH * 9) g_M1[i] = 0.f;
        if (i < BATCH * 3) g_mm[i] = 0.f;
    }
    const unsigned PER = 16u * 2048u * 128u;  // float4 groups per tensor
    unsigned idx = blockIdx.x * blockDim.x + threadIdx.x;
    if (idx >= 2u * PER) return;
    bool isK = idx >= PER;
    unsigned i = isK ? idx - PER : idx;
    size_t e = (size_t)i * 4;
    float4 v = *(const float4*)((isK ? te : se) + e);
    if (!isK) { const float s = 1.f / 3.f; v.x *= s; v.y *= s; v.z *= s; v.w *= s; }
    __half h0 = __float2half_rn(v.x), h1 = __float2half_rn(v.y);
    __half h2 = __float2half_rn(v.z), h3 = __float2half_rn(v.w);
    __half l0 = __float2half_rn(v.x - __half2float(h0));
    __half l1 = __float2half_rn(v.y - __half2float(h1));
    __half l2 = __float2half_rn(v.z - __half2float(h2));
    __half l3 = __float2half_rn(v.w - __half2float(h3));
    uint2 hp, lp;
    hp.x = (uint32_t)__half_as_ushort(h0) | ((uint32_t)__half_as_ushort(h1) << 16);
    hp.y = (uint32_t)__half_as_ushort(h2) | ((uint32_t)__half_as_ushort(h3) << 16);
    lp.x = (uint32_t)__half_as_ushort(l0) | ((uint32_t)__half_as_ushort(l1) << 16);
    lp.y = (uint32_t)__half_as_ushort(l2) | ((uint32_t)__half_as_ushort(l3) << 16);
    if (isK) { *(uint2*)(g_Kh + e) = hp; *(uint2*)(g_Kl + e) = lp; }
    else     { *(uint2*)(g_Qh + e) = hp; *(uint2*)(g_Ql + e) = lp; }
}

// Flash-style streaming attention, fp16 hi/lo 3-GEMM, 512 threads (4x4 warps).
// Chunk = k64 of one key tile; stage = {Qh,Ql,Kh,Kl}[128r x 64k] = 64KB; 3 stages.
#define STAGE_SZ 65536
#define NSTAGE   3
__global__ void __launch_bounds__(512, 1)
attn_mma_kernel(const float* __restrict__ src, const float* __restrict__ tgt) {
    extern __shared__ unsigned char dyn_smem[];
    __shared__ float4 v_smem[128];
    __shared__ float  red[128][4];
    const uint32_t sb = smem_u32(dyn_smem);
    const int tid = threadIdx.x, lane = tid & 31, wid = tid >> 5;
    const int wm = wid >> 2, wn = wid & 3;  // 4x4 warp grid: 32m x 32n
    const int b = blockIdx.x >> 4, qt = blockIdx.x & 15;

    if (tid < 128) { red[tid][0] = 0.f; red[tid][1] = 0.f; red[tid][2] = 0.f; red[tid][3] = 0.f; }

    float acc[2][4][4];
    #pragma unroll
    for (int s = 0; s < 2; s++)
        #pragma unroll
        for (int ns = 0; ns < 4; ns++)
            #pragma unroll
            for (int c = 0; c < 4; c++) acc[s][ns][c] = 0.f;
    float den[4] = {0, 0, 0, 0}, num[4][3] = {};

    const int la_row = ((lane >> 3) & 1) * 8 + (lane & 7);
    const int la_k   = (lane >> 4) & 1;
    const int lb_row = ((lane >> 4) & 1) * 8 + (lane & 7);
    const int lb_k   = (lane >> 3) & 1;

    // issue chunk cidx (kt = cidx>>3, kc = cidx&7) into stage st
    auto issue = [&](int cidx, int st) {
        const int kt = cidx >> 3, kc = cidx & 7;
        const uint32_t base = sb + st * STAGE_SZ;
        // 64KB / 512 thr / 16B = 8 CPA per thread: 2 per buffer
        #pragma unroll
        for (int r = 0; r < 2; r++) {
            int lin = tid + r * 512;           // 0..1023
            int row = lin >> 3, kg = lin & 7;
            uint32_t off = (uint32_t)row * 128u + (uint32_t)((kg ^ (row & 7)) << 4);
            size_t qe = ((size_t)(b * NPTS + qt * 128 + row)) * DIM + kc * 64 + kg * 8;
            size_t ke = ((size_t)(b * NPTS + kt * 128 + row)) * DIM + kc * 64 + kg * 8;
            CPA(base + off,         g_Qh + qe);
            CPA(base + 16384 + off, g_Ql + qe);
            CPA(base + 32768 + off, g_Kh + ke);
            CPA(base + 49152 + off, g_Kl + ke);
        }
    };

    __syncthreads();
    issue(0, 0); CPC();
    issue(1, 1); CPC();

    for (int cidx = 0; cidx < 128; cidx++) {
        const int st = cidx % NSTAGE;
        if (cidx + 2 < 128) { issue(cidx + 2, (cidx + 2) % NSTAGE); CPC(); CPW(2); }
        else if (cidx + 1 < 128) { CPW(1); }
        else { CPW(0); }
        __syncthreads();

        const uint32_t qh = sb + st * STAGE_SZ, ql = qh + 16384;
        const uint32_t kh = qh + 32768,         kl = qh + 49152;
        #pragma unroll
        for (int jj = 0; jj < 4; jj++) {
            uint32_t ah[8], al[8];
            #pragma unroll
            for (int s = 0; s < 2; s++) {
                int row = wm * 32 + s * 16 + la_row;
                uint32_t off = (uint32_t)row * 128u +
                               (uint32_t)(((jj * 2 + la_k) ^ (row & 7)) << 4);
                ldm4(ah + s * 4, qh + off);
                ldm4(al + s * 4, ql + off);
            }
            #pragma unroll
            for (int g = 0; g < 2; g++) {
                int row = wn * 32 + g * 16 + lb_row;
                uint32_t off = (uint32_t)row * 128u +
                               (uint32_t)(((jj * 2 + lb_k) ^ (row & 7)) << 4);
                uint32_t bh[4], bl[4];
                ldm4(bh, kh + off);
                ldm4(bl, kl + off);
                #pragma unroll
                for (int h = 0; h < 2; h++) {
                    #pragma unroll
                    for (int s = 0; s < 2; s++) {
                        float* a = acc[s][g * 2 + h];
                        mma16816(a, ah + s * 4, bh[h * 2], bh[h * 2 + 1]);
                        mma16816(a, al + s * 4, bh[h * 2], bh[h * 2 + 1]);
                        mma16816(a, ah + s * 4, bl[h * 2], bl[h * 2 + 1]);
                    }
                }
            }
        }

        if ((cidx & 7) == 7) {  // key tile complete: softmax-stream epilogue
            const int kt = cidx >> 3;
            __syncthreads();
            if (tid < 128) {
                const float* vp = tgt + ((size_t)(b * NPTS + kt * 128 + tid)) * 3;
                v_smem[tid] = make_float4(vp[0], vp[1], vp[2], 0.f);
            }
            __syncthreads();
            #pragma unroll
            for (int ns = 0; ns < 4; ns++) {
                float4 v0 = v_smem[wn * 32 + ns * 8 + 2 * (lane & 3)];
                float4 v1 = v_smem[wn * 32 + ns * 8 + 2 * (lane & 3) + 1];
                #pragma unroll
                for (int s = 0; s < 2; s++) {
                    #pragma unroll
                    for (int cp = 0; cp < 2; cp++) {
                        float e0 = __expf(acc[s][ns][cp * 2]);
                        float e1 = __expf(acc[s][ns][cp * 2 + 1]);
                        int qi = s * 2 + cp;
                        den[qi] += e0 + e1;
                        num[qi][0] += e0 * v0.x + e1 * v1.x;
                        num[qi][1] += e0 * v0.y + e1 * v1.y;
                        num[qi][2] += e0 * v0.z + e1 * v1.z;
                        acc[s][ns][cp * 2] = 0.f;
                        acc[s][ns][cp * 2 + 1] = 0.f;
                    }
                }
            }
        }
        __syncthreads();
    }

    // reduce over the 4 lanes sharing each query row
    #pragma unroll
    for (int o = 1; o <= 2; o <<= 1) {
        #pragma unroll
        for (int qi = 0; qi < 4; qi++) {
            den[qi] += __shfl_xor_sync(0xFFFFFFFFu, den[qi], o);
            num[qi][0] += __shfl_xor_sync(0xFFFFFFFFu, num[qi][0], o);
            num[qi][1] += __shfl_xor_sync(0xFFFFFFFFu, num[qi][1], o);
            num[qi][2] += __shfl_xor_sync(0xFFFFFFFFu, num[qi][2], o);
        }
    }
    if ((lane & 3) == 0) {
        #pragma unroll
        for (int qi = 0; qi < 4; qi++) {
            int q = wm * 32 + (qi >> 1) * 16 + (qi & 1) * 8 + (lane >> 2);
            atomicAdd(&red[q][0], den[qi]);
            atomicAdd(&red[q][1], num[qi][0]);
            atomicAdd(&red[q][2], num[qi][1]);
            atomicAdd(&red[q][3], num[qi][2]);
        }
    }
    __syncthreads();

    if (tid < 128) {
        const int n = qt * 128 + tid;
        const float inv = 1.f / red[tid][0];
        const float m0 = red[tid][1] * inv, m1 = red[tid][2] * inv, m2 = red[tid][3] * inv;
        const float* sp = src + ((size_t)(b * NPTS + n)) * 3;
        const float s0 = __ldg(sp), s1 = __ldg(sp + 1), s2 = __ldg(sp + 2);
        float vals[12] = { s0 * m0, s0 * m1, s0 * m2, s1 * m0, s1 * m1, s1 * m2,
                           s2 * m0, s2 * m1, s2 * m2, m0, m1, m2 };
        #pragma unroll
        for (int o = 16; o; o >>= 1)
            #pragma unroll
            for (int i = 0; i < 12; i++)
                vals[i] += __shfl_xor_sync(0xFFFFFFFFu, vals[i], o);
        if (lane == 0) {
            #pragma unroll
            for (int i = 0; i < 9; i++) atomicAdd(&g_M1[b * 9 + i], vals[i]);
            #pragma unroll
            for (int c = 0; c < 3; c++) atomicAdd(&g_mm[b * 3 + c], vals[9 + c]);
        }
    }
}

// R = polar(H^T) via scaled Newton in fp32 (== V U^T of SVD), reflection fix, t.
__global__ void finalize_kernel(const float* __restrict__ src, float* __restrict__ out) {
    const int b = blockIdx.x, tid = threadIdx.x;
    __shared__ float red[256 * 3];
    float s0 = 0.f, s1 = 0.f, s2 = 0.f;
    const float* sb = src + (size_t)b * NPTS * 3;
    for (int n = tid; n < NPTS; n += 256) {
        s0 += sb[n * 3]; s1 += sb[n * 3 + 1]; s2 += sb[n * 3 + 2];
    }
    red[tid * 3] = s0; red[tid * 3 + 1] = s1; red[tid * 3 + 2] = s2;
    __syncthreads();
    for (int s = 128; s; s >>= 1) {
        if (tid < s)
            for (int c = 0; c < 3; c++) red[tid * 3 + c] += red[(tid + s) * 3 + c];
        __syncthreads();
    }
    if (tid == 0) {
        const float Nd = (float)NPTS;
        float sm[3] = { red[0] / Nd, red[1] / Nd, red[2] / Nd };
        float mm[3] = { g_mm[b*3] / Nd, g_mm[b*3+1] / Nd, g_mm[b*3+2] / Nd };
        float A[3][3]; float f = 0.f;
        for (int i = 0; i < 3; i++)
            for (int j = 0; j < 3; j++) {
                float h = g_M1[b * 9 + j * 3 + i] - Nd * sm[j] * mm[i];
                A[i][j] = h; f += h * h;   // A = H^T
            }
        f = rsqrtf(f);
        for (int i = 0; i < 3; i++)
            for (int j = 0; j < 3; j++) A[i][j] *= f;
        for (int it = 0; it < 18; it++) {
            float C[3][3];
            C[0][0] =  A[1][1]*A[2][2] - A[1][2]*A[2][1];
            C[0][1] = -(A[1][0]*A[2][2] - A[1][2]*A[2][0]);
            C[0][2] =  A[1][0]*A[2][1] - A[1][1]*A[2][0];
            C[1][0] = -(A[0][1]*A[2][2] - A[0][2]*A[2][1]);
            C[1][1] =  A[0][0]*A[2][2] - A[0][2]*A[2][0];
            C[1][2] = -(A[0][0]*A[2][1] - A[0][1]*A[2][0]);
            C[2][0] =  A[0][1]*A[1][2] - A[0][2]*A[1][1];
            C[2][1] = -(A[0][0]*A[1][2] - A[0][2]*A[1][0]);
            C[2][2] =  A[0][0]*A[1][1] - A[0][1]*A[1][0];
            float det = A[0][0]*C[0][0] + A[0][1]*C[0][1] + A[0][2]*C[0][2];
            float mu = 1.f / cbrtf(fabsf(det));
            float idm = 1.f / (det * mu);
            for (int i = 0; i < 3; i++)
                for (int j = 0; j < 3; j++)
                    A[i][j] = 0.5f * (mu * A[i][j] + C[i][j] * idm);
        }
        float detR = A[0][0]*(A[1][1]*A[2][2]-A[1][2]*A[2][1])
                   - A[0][1]*(A[1][0]*A[2][2]-A[1][2]*A[2][0])
                   + A[0][2]*(A[1][0]*A[2][1]-A[1][1]*A[2][0]);
        if (detR < 0.f) { A[2][0] = -A[2][0]; A[2][1] = -A[2][1]; A[2][2] = -A[2][2]; }
        for (int i = 0; i < 3; i++)
            for (int j = 0; j < 3; j++)
                out[b * 9 + i * 3 + j] = A[i][j];
        for (int j = 0; j < 3; j++)
            out[BATCH * 9 + b * 3 + j] =
                mm[j] - (sm[0] * A[j][0] + sm[1] * A[j][1] + sm[2] * A[j][2]);
    }
}

// Pad launch so ncu -s 5 -c 1 lands on attn_mma_kernel (4 launches/iter).
__global__ void pad_kernel() {}

extern "C" void kernel_launch(void* const* d_in, const int* in_sizes, int n_in,
                              void* d_out, int out_size) {
    const float* src = (const float*)d_in[0];
    const float* tgt = (const float*)d_in[1];
    const float* src_embed = (const float*)d_in[2];
    const float* tgt_embed = (const float*)d_in[3];
    float* out = (float*)d_out;

    static int init_done = 0;
    if (!init_done) {
        cudaFuncSetAttribute(attn_mma_kernel,
                             cudaFuncAttributeMaxDynamicSharedMemorySize, NSTAGE * STAGE_SZ);
        init_done = 1;
    }
    prep_kernel<<<32768, 256>>>(src_embed, tgt_embed);
    attn_mma_kernel<<<BATCH * 16, 512, NSTAGE * STAGE_SZ>>>(src, tgt);
    finalize_kernel<<<BATCH, 256>>>(src, out);
    pad_kernel<<<1, 32>>>();
}

// round 8
// speedup vs baseline: 7.0943x; 1.5320x over previous
#include <cuda_runtime.h>
#include <math.h>
#include <stdint.h>

#define BATCH 16
#define NPTS  2048
#define DIM   512
#define NROWS (BATCH * NPTS)

// int8 quantized embeddings, row-major [B][N][D]: x = sq*(qa + qb/254)
__device__ __align__(16) signed char g_Qa[NROWS * DIM];
__device__ __align__(16) signed char g_Qb[NROWS * DIM];
__device__ __align__(16) signed char g_Ka[NROWS * DIM];
__device__ __align__(16) signed char g_Kb[NROWS * DIM];
__device__ float g_Sq[NROWS];   // includes 1/3 fold for Q
__device__ float g_Sk[NROWS];
__device__ float g_M1[BATCH * 9];
__device__ float g_mm[BATCH * 3];

__device__ __forceinline__ uint32_t smem_u32(const void* p) {
    uint32_t a;
    asm("{ .reg .u64 t; cvta.to.shared.u64 t, %1; cvt.u32.u64 %0, t; }" : "=r"(a) : "l"(p));
    return a;
}
#define CPA(dst, src) \
    asm volatile("cp.async.cg.shared.global [%0], [%1], 16;" :: "r"(dst), "l"(src) : "memory")
#define CPC() asm volatile("cp.async.commit_group;" ::: "memory")
#define CPW(n) asm volatile("cp.async.wait_group %0;" :: "n"(n) : "memory")

__device__ __forceinline__ void ldm4(uint32_t* r, uint32_t a) {
    asm volatile("ldmatrix.sync.aligned.m8n8.x4.shared.b16 {%0,%1,%2,%3}, [%4];"
                 : "=r"(r[0]), "=r"(r[1]), "=r"(r[2]), "=r"(r[3]) : "r"(a));
}
__device__ __forceinline__ void mma_s8(int* c, const uint32_t* a, uint32_t b0, uint32_t b1) {
    asm volatile("mma.sync.aligned.m16n8k32.row.col.s32.s8.s8.s32 "
                 "{%0,%1,%2,%3},{%4,%5,%6,%7},{%8,%9},{%0,%1,%2,%3};"
                 : "+r"(c[0]), "+r"(c[1]), "+r"(c[2]), "+r"(c[3])
                 : "r"(a[0]), "r"(a[1]), "r"(a[2]), "r"(a[3]), "r"(b0), "r"(b1));
}

// One warp per row: rowmax -> per-row scale -> 2-term int8 quantization.
__global__ void __launch_bounds__(256) prep_kernel(
    const float* __restrict__ se, const float* __restrict__ te) {
    if (blockIdx.x == 0 && threadIdx.x < 192) {
        int i = threadIdx.x;
        if (i < BATCH * 9) g_M1[i] = 0.f;
        if (i < BATCH * 3) g_mm[i] = 0.f;
    }
    const int lane = threadIdx.x & 31;
    int grow = blockIdx.x * 8 + (threadIdx.x >> 5);   // 0 .. 2*NROWS-1
    bool isK = grow >= NROWS;
    int row = isK ? grow - NROWS : grow;
    const float* sp = (isK ? te : se) + (size_t)row * DIM;
    const float qs = isK ? 1.f : (1.f / 3.f);

    float4 v[4];
    float vmax = 0.f;
    #pragma unroll
    for (int i = 0; i < 4; i++) {
        v[i] = *(const float4*)(sp + 4 * (lane + 32 * i));
        v[i].x *= qs; v[i].y *= qs; v[i].z *= qs; v[i].w *= qs;
        vmax = fmaxf(vmax, fmaxf(fmaxf(fabsf(v[i].x), fabsf(v[i].y)),
                                 fmaxf(fabsf(v[i].z), fabsf(v[i].w))));
    }
    #pragma unroll
    for (int o = 16; o; o >>= 1)
        vmax = fmaxf(vmax, __shfl_xor_sync(0xFFFFFFFFu, vmax, o));
    vmax = fmaxf(vmax, 1e-30f);
    const float sq = vmax * (1.f / 127.f);
    const float i1 = 127.f / vmax;
    const float i2 = 254.f / sq;

    signed char* pa = (isK ? g_Ka : g_Qa) + (size_t)row * DIM;
    signed char* pb = (isK ? g_Kb : g_Qb) + (size_t)row * DIM;
    #pragma unroll
    for (int i = 0; i < 4; i++) {
        float x[4] = { v[i].x, v[i].y, v[i].z, v[i].w };
        uint32_t wa = 0, wb = 0;
        #pragma unroll
        for (int j = 0; j < 4; j++) {
            int a = __float2int_rn(x[j] * i1);
            float r = x[j] - (float)a * sq;
            int bq = __float2int_rn(r * i2);
            wa |= ((uint32_t)(a & 255)) << (8 * j);
            wb |= ((uint32_t)(bq & 255)) << (8 * j);
        }
        ((uint32_t*)pa)[lane + 32 * i] = wa;
        ((uint32_t*)pb)[lane + 32 * i] = wb;
    }
    if (lane == 0) { if (isK) g_Sk[row] = sq; else g_Sq[row] = sq; }
}

// Flash attention on IMMA s8: 512 threads (4x4 warps, 32m x 32n per warp).
// Chunk = k64; stage = {Qa,Qb,Ka,Kb}[128r x 64] = 32KB; 4 stages, prefetch 3.
#define STAGE_SZ 32768
#define NSTAGE   4
__global__ void __launch_bounds__(512, 1)
attn_mma_kernel(const float* __restrict__ src, const float* __restrict__ tgt) {
    extern __shared__ unsigned char dyn_smem[];
    __shared__ float4 v_smem[128];
    __shared__ float  red[128][4];
    const uint32_t sb = smem_u32(dyn_smem);
    const int tid = threadIdx.x, lane = tid & 31, wid = tid >> 5;
    const int wm = wid >> 2, wn = wid & 3;
    const int b = blockIdx.x >> 4, qt = blockIdx.x & 15;

    if (tid < 128) { red[tid][0] = 0.f; red[tid][1] = 0.f; red[tid][2] = 0.f; red[tid][3] = 0.f; }

    int acc1[2][4][4], accX[2][4][4];
    #pragma unroll
    for (int s = 0; s < 2; s++)
        #pragma unroll
        for (int ns = 0; ns < 4; ns++)
            #pragma unroll
            for (int c = 0; c < 4; c++) { acc1[s][ns][c] = 0; accX[s][ns][c] = 0; }
    float den[4] = {0, 0, 0, 0}, num[4][3] = {};

    // per-thread query-row scales (rows: wm*32 + s*16 + cp*8 + lane>>2)
    float sqv[4];
    #pragma unroll
    for (int qi = 0; qi < 4; qi++)
        sqv[qi] = g_Sq[b * NPTS + qt * 128 + wm * 32 + (qi >> 1) * 16 + (qi & 1) * 8 + (lane >> 2)];

    const int la_row = ((lane >> 3) & 1) * 8 + (lane & 7);
    const int la_k   = (lane >> 4) & 1;
    const int lb_row = ((lane >> 4) & 1) * 8 + (lane & 7);
    const int lb_k   = (lane >> 3) & 1;

    // issue chunk cidx (kt = cidx>>3, kc = cidx&7) into stage st
    auto issue = [&](int cidx, int st) {
        const int kt = cidx >> 3, kc = cidx & 7;
        const uint32_t base = sb + st * STAGE_SZ;
        const int row = tid >> 2, g = tid & 3;
        uint32_t off = (uint32_t)row * 64u + (uint32_t)((g ^ ((row >> 1) & 3)) << 4);
        size_t qe = ((size_t)(b * NPTS + qt * 128 + row)) * DIM + kc * 64 + g * 16;
        size_t ke = ((size_t)(b * NPTS + kt * 128 + row)) * DIM + kc * 64 + g * 16;
        CPA(base + off,         g_Qa + qe);
        CPA(base + 8192 + off,  g_Qb + qe);
        CPA(base + 16384 + off, g_Ka + ke);
        CPA(base + 24576 + off, g_Kb + ke);
    };

    __syncthreads();
    issue(0, 0); CPC();
    issue(1, 1); CPC();
    issue(2, 2); CPC();

    for (int cidx = 0; cidx < 128; cidx++) {
        const int st = cidx & 3;
        if (cidx + 3 < 128) { issue(cidx + 3, (cidx + 3) & 3); CPC(); CPW(3); }
        else if (cidx + 2 < 128) { CPW(2); }
        else if (cidx + 1 < 128) { CPW(1); }
        else { CPW(0); }
        __syncthreads();

        const uint32_t qa = sb + st * STAGE_SZ, qb = qa + 8192;
        const uint32_t ka = qa + 16384,         kb = qa + 24576;
        #pragma unroll
        for (int jj = 0; jj < 2; jj++) {
            uint32_t ah[8], al[8];
            #pragma unroll
            for (int s = 0; s < 2; s++) {
                int row = wm * 32 + s * 16 + la_row;
                uint32_t off = (uint32_t)row * 64u +
                               (uint32_t)(((jj * 2 + la_k) ^ ((row >> 1) & 3)) << 4);
                ldm4(ah + s * 4, qa + off);
                ldm4(al + s * 4, qb + off);
            }
            #pragma unroll
            for (int g = 0; g < 2; g++) {
                int row = wn * 32 + g * 16 + lb_row;
                uint32_t off = (uint32_t)row * 64u +
                               (uint32_t)(((jj * 2 + lb_k) ^ ((row >> 1) & 3)) << 4);
                uint32_t bh[4], bl[4];
                ldm4(bh, ka + off);
                ldm4(bl, kb + off);
                #pragma unroll
                for (int h = 0; h < 2; h++) {
                    #pragma unroll
                    for (int s = 0; s < 2; s++) {
                        mma_s8(acc1[s][g * 2 + h], ah + s * 4, bh[h * 2], bh[h * 2 + 1]);
                        mma_s8(accX[s][g * 2 + h], ah + s * 4, bl[h * 2], bl[h * 2 + 1]);
                        mma_s8(accX[s][g * 2 + h], al + s * 4, bh[h * 2], bh[h * 2 + 1]);
                    }
                }
            }
        }

        if ((cidx & 7) == 7) {  // key tile done: logits -> exp -> streaming sums
            const int kt = cidx >> 3;
            __syncthreads();
            if (tid < 128) {
                const float* vp = tgt + ((size_t)(b * NPTS + kt * 128 + tid)) * 3;
                v_smem[tid] = make_float4(vp[0], vp[1], vp[2],
                                          g_Sk[b * NPTS + kt * 128 + tid]);
            }
            __syncthreads();
            #pragma unroll
            for (int ns = 0; ns < 4; ns++) {
                float4 v0 = v_smem[wn * 32 + ns * 8 + 2 * (lane & 3)];
                float4 v1 = v_smem[wn * 32 + ns * 8 + 2 * (lane & 3) + 1];
                #pragma unroll
                for (int s = 0; s < 2; s++) {
                    #pragma unroll
                    for (int cp = 0; cp < 2; cp++) {
                        int qi = s * 2 + cp;
                        float d0 = __int2float_rn(acc1[s][ns][cp * 2]) +
                                   __int2float_rn(accX[s][ns][cp * 2]) * (1.f / 254.f);
                        float d1 = __int2float_rn(acc1[s][ns][cp * 2 + 1]) +
                                   __int2float_rn(accX[s][ns][cp * 2 + 1]) * (1.f / 254.f);
                        float e0 = __expf(sqv[qi] * v0.w * d0);
                        float e1 = __expf(sqv[qi] * v1.w * d1);
                        den[qi] += e0 + e1;
                        num[qi][0] += e0 * v0.x + e1 * v1.x;
                        num[qi][1] += e0 * v0.y + e1 * v1.y;
                        num[qi][2] += e0 * v0.z + e1 * v1.z;
                        acc1[s][ns][cp * 2] = 0;     accX[s][ns][cp * 2] = 0;
                        acc1[s][ns][cp * 2 + 1] = 0; accX[s][ns][cp * 2 + 1] = 0;
                    }
                }
            }
        }
        __syncthreads();
    }

    #pragma unroll
    for (int o = 1; o <= 2; o <<= 1) {
        #pragma unroll
        for (int qi = 0; qi < 4; qi++) {
            den[qi] += __shfl_xor_sync(0xFFFFFFFFu, den[qi], o);
            num[qi][0] += __shfl_xor_sync(0xFFFFFFFFu, num[qi][0], o);
            num[qi][1] += __shfl_xor_sync(0xFFFFFFFFu, num[qi][1], o);
            num[qi][2] += __shfl_xor_sync(0xFFFFFFFFu, num[qi][2], o);
        }
    }
    if ((lane & 3) == 0) {
        #pragma unroll
        for (int qi = 0; qi < 4; qi++) {
            int q = wm * 32 + (qi >> 1) * 16 + (qi & 1) * 8 + (lane >> 2);
            atomicAdd(&red[q][0], den[qi]);
            atomicAdd(&red[q][1], num[qi][0]);
            atomicAdd(&red[q][2], num[qi][1]);
            atomicAdd(&red[q][3], num[qi][2]);
        }
    }
    __syncthreads();

    if (tid < 128) {
        const int n = qt * 128 + tid;
        const float inv = 1.f / red[tid][0];
        const float m0 = red[tid][1] * inv, m1 = red[tid][2] * inv, m2 = red[tid][3] * inv;
        const float* sp = src + ((size_t)(b * NPTS + n)) * 3;
        const float s0 = __ldg(sp), s1 = __ldg(sp + 1), s2 = __ldg(sp + 2);
        float vals[12] = { s0 * m0, s0 * m1, s0 * m2, s1 * m0, s1 * m1, s1 * m2,
                           s2 * m0, s2 * m1, s2 * m2, m0, m1, m2 };
        #pragma unroll
        for (int o = 16; o; o >>= 1)
            #pragma unroll
            for (int i = 0; i < 12; i++)
                vals[i] += __shfl_xor_sync(0xFFFFFFFFu, vals[i], o);
        if (lane == 0) {
            #pragma unroll
            for (int i = 0; i < 9; i++) atomicAdd(&g_M1[b * 9 + i], vals[i]);
            #pragma unroll
            for (int c = 0; c < 3; c++) atomicAdd(&g_mm[b * 3 + c], vals[9 + c]);
        }
    }
}

// R = polar(H^T) via scaled Newton (== V U^T of SVD), reflection fix, t.
__global__ void finalize_kernel(const float* __restrict__ src, float* __restrict__ out) {
    const int b = blockIdx.x, tid = threadIdx.x;
    __shared__ float red[256 * 3];
    float s0 = 0.f, s1 = 0.f, s2 = 0.f;
    const float* sb = src + (size_t)b * NPTS * 3;
    for (int n = tid; n < NPTS; n += 256) {
        s0 += sb[n * 3]; s1 += sb[n * 3 + 1]; s2 += sb[n * 3 + 2];
    }
    red[tid * 3] = s0; red[tid * 3 + 1] = s1; red[tid * 3 + 2] = s2;
    __syncthreads();
    for (int s = 128; s; s >>= 1) {
        if (tid < s)
            for (int c = 0; c < 3; c++) red[tid * 3 + c] += red[(tid + s) * 3 + c];
        __syncthreads();
    }
    if (tid == 0) {
        const float Nd = (float)NPTS;
        float sm[3] = { red[0] / Nd, red[1] / Nd, red[2] / Nd };
        float mm[3] = { g_mm[b*3] / Nd, g_mm[b*3+1] / Nd, g_mm[b*3+2] / Nd };
        float A[3][3]; float f = 0.f;
        for (int i = 0; i < 3; i++)
            for (int j = 0; j < 3; j++) {
                float h = g_M1[b * 9 + j * 3 + i] - Nd * sm[j] * mm[i];
                A[i][j] = h; f += h * h;   // A = H^T
            }
        f = rsqrtf(f);
        for (int i = 0; i < 3; i++)
            for (int j = 0; j < 3; j++) A[i][j] *= f;
        for (int it = 0; it < 18; it++) {
            float C[3][3];
            C[0][0] =  A[1][1]*A[2][2] - A[1][2]*A[2][1];
            C[0][1] = -(A[1][0]*A[2][2] - A[1][2]*A[2][0]);
            C[0][2] =  A[1][0]*A[2][1] - A[1][1]*A[2][0];
            C[1][0] = -(A[0][1]*A[2][2] - A[0][2]*A[2][1]);
            C[1][1] =  A[0][0]*A[2][2] - A[0][2]*A[2][0];
            C[1][2] = -(A[0][0]*A[2][1] - A[0][1]*A[2][0]);
            C[2][0] =  A[0][1]*A[1][2] - A[0][2]*A[1][1];
            C[2][1] = -(A[0][0]*A[1][2] - A[0][2]*A[1][0]);
            C[2][2] =  A[0][0]*A[1][1] - A[0][1]*A[1][0];
            float det = A[0][0]*C[0][0] + A[0][1]*C[0][1] + A[0][2]*C[0][2];
            float mu = 1.f / cbrtf(fabsf(det));
            float idm = 1.f / (det * mu);
            for (int i = 0; i < 3; i++)
                for (int j = 0; j < 3; j++)
                    A[i][j] = 0.5f * (mu * A[i][j] + C[i][j] * idm);
        }
        float detR = A[0][0]*(A[1][1]*A[2][2]-A[1][2]*A[2][1])
                   - A[0][1]*(A[1][0]*A[2][2]-A[1][2]*A[2][0])
                   + A[0][2]*(A[1][0]*A[2][1]-A[1][1]*A[2][0]);
        if (detR < 0.f) { A[2][0] = -A[2][0]; A[2][1] = -A[2][1]; A[2][2] = -A[2][2]; }
        for (int i = 0; i < 3; i++)
            for (int j = 0; j < 3; j++)
                out[b * 9 + i * 3 + j] = A[i][j];
        for (int j = 0; j < 3; j++)
            out[BATCH * 9 + b * 3 + j] =
                mm[j] - (sm[0] * A[j][0] + sm[1] * A[j][1] + sm[2] * A[j][2]);
    }
}

extern "C" void kernel_launch(void* const* d_in, const int* in_sizes, int n_in,
                              void* d_out, int out_size) {
    const float* src = (const float*)d_in[0];
    const float* tgt = (const float*)d_in[1];
    const float* src_embed = (const float*)d_in[2];
    const float* tgt_embed = (const float*)d_in[3];
    float* out = (float*)d_out;

    static int init_done = 0;
    if (!init_done) {
        cudaFuncSetAttribute(attn_mma_kernel,
                             cudaFuncAttributeMaxDynamicSharedMemorySize, NSTAGE * STAGE_SZ);
        init_done = 1;
    }
    prep_kernel<<<8192, 256>>>(src_embed, tgt_embed);
    attn_mma_kernel<<<BATCH * 16, 512, NSTAGE * STAGE_SZ>>>(src, tgt);
    finalize_kernel<<<BATCH, 256>>>(src, out);
}